// round 15
// baseline (speedup 1.0000x reference)
#include <cuda_runtime.h>
#include <cuda_fp16.h>
#include <math.h>
#include <cstdint>

using fp16 = __half;

static constexpr int L_ = 6, D_ = 1024, H_ = 16, F_ = 4096, S_ = 512, B_ = 16, P_ = 512;
static constexpr int DH_ = D_ / H_;
static constexpr int M_ = B_ * S_;
static constexpr int D3 = 3 * D_;

// ---------------- scratch ----------------------------------------------------
__device__ __align__(16) float g_h[(size_t)M_ * D_];
__device__ __align__(16) float g_out1[(size_t)M_ * D_];

__device__ __align__(16) fp16 g_xn[(size_t)M_ * D_];
__device__ __align__(16) fp16 g_qkv[(size_t)M_ * D3];
__device__ __align__(16) fp16 g_ctx[(size_t)M_ * D_];
__device__ __align__(16) fp16 g_f1[(size_t)M_ * F_];

__device__ __align__(16) fp16 g_wqkvT[(size_t)L_ * D3 * D_];
__device__ __align__(16) fp16 g_woT[(size_t)L_ * D_ * D_];
__device__ __align__(16) fp16 g_w1T[(size_t)L_ * D_ * F_];
__device__ __align__(16) fp16 g_w2T[(size_t)L_ * F_ * D_];
__device__ __align__(16) float g_bqkv[(size_t)L_ * D3];

// ---------------- PTX helpers -------------------------------------------------
__device__ __forceinline__ uint32_t smem_u32(const void* p) {
    uint32_t a;
    asm("{ .reg .u64 t; cvta.to.shared.u64 t, %1; cvt.u32.u64 %0, t; }" : "=r"(a) : "l"(p));
    return a;
}
__device__ __forceinline__ void ldsm4(uint32_t* r, uint32_t addr) {
    asm volatile("ldmatrix.sync.aligned.m8n8.x4.shared.b16 {%0,%1,%2,%3}, [%4];"
                 : "=r"(r[0]), "=r"(r[1]), "=r"(r[2]), "=r"(r[3]) : "r"(addr));
}
__device__ __forceinline__ void ldsm4t(uint32_t* r, uint32_t addr) {
    asm volatile("ldmatrix.sync.aligned.m8n8.x4.trans.shared.b16 {%0,%1,%2,%3}, [%4];"
                 : "=r"(r[0]), "=r"(r[1]), "=r"(r[2]), "=r"(r[3]) : "r"(addr));
}
__device__ __forceinline__ void mma16816h(float* d, const uint32_t* a, uint32_t b0, uint32_t b1) {
    asm volatile("mma.sync.aligned.m16n8k16.row.col.f32.f16.f16.f32 "
                 "{%0,%1,%2,%3}, {%4,%5,%6,%7}, {%8,%9}, {%0,%1,%2,%3};"
                 : "+f"(d[0]), "+f"(d[1]), "+f"(d[2]), "+f"(d[3])
                 : "r"(a[0]), "r"(a[1]), "r"(a[2]), "r"(a[3]), "r"(b0), "r"(b1));
}
#define CPA(dst, src)  asm volatile("cp.async.cg.shared.global [%0], [%1], 16;" :: "r"(dst), "l"(src))
#define CPA_COMMIT()   asm volatile("cp.async.commit_group;" ::: "memory")
#define CPA_WAIT2()    asm volatile("cp.async.wait_group 2;" ::: "memory")
#define CPA_WAIT1()    asm volatile("cp.async.wait_group 1;" ::: "memory")
#define CPA_WAIT0()    asm volatile("cp.async.wait_group 0;" ::: "memory")

__device__ __forceinline__ uint32_t swz(uint32_t off) { return off ^ ((off >> 3) & 0x70); }
__device__ __forceinline__ uint32_t smx(uint32_t r, uint32_t c) { return r + (c ^ ((r >> 3) & 0x70)); }

// ---------------- h = x + pe -------------------------------------------------
__global__ __launch_bounds__(256) void addpe_kernel(const float* __restrict__ x,
                                                    const float* __restrict__ pe,
                                                    float* __restrict__ h) {
    int i = blockIdx.x * 256 + threadIdx.x;
    h[i] = x[i] + pe[i & (S_ * D_ - 1)];
}

// ---------------- pack qkv bias ----------------------------------------------
__global__ __launch_bounds__(256) void packb_kernel(const float* __restrict__ bq,
                                                    const float* __restrict__ bk,
                                                    const float* __restrict__ bv,
                                                    float* __restrict__ o) {
    int l = blockIdx.y;
    int i = blockIdx.x * 256 + threadIdx.x;
    o[(size_t)l * D3 + i]          = bq[l * D_ + i];
    o[(size_t)l * D3 + D_ + i]     = bk[l * D_ + i];
    o[(size_t)l * D3 + 2 * D_ + i] = bv[l * D_ + i];
}

// ---------------- weight transpose: W[K,N] -> T[N,K] fp16 --------------------
__global__ __launch_bounds__(256) void wtrans_kernel(const float* __restrict__ W,
                                                     fp16* __restrict__ T,
                                                     int K, int N, size_t out_ls) {
    __shared__ float t[32][33];
    size_t inoff  = (size_t)blockIdx.z * K * N;
    size_t outoff = (size_t)blockIdx.z * out_ls;
    int k0 = blockIdx.y * 32, n0 = blockIdx.x * 32;
    int tx = threadIdx.x & 31, ty = threadIdx.x >> 5;
#pragma unroll
    for (int i = 0; i < 32; i += 8)
        t[ty + i][tx] = W[inoff + (size_t)(k0 + ty + i) * N + n0 + tx];
    __syncthreads();
#pragma unroll
    for (int i = 0; i < 32; i += 8)
        T[outoff + (size_t)(n0 + ty + i) * K + k0 + tx] = __float2half_rn(t[tx][ty + i]);
}

// merged q/k/v transpose -> fused [D3,K] fp16
__global__ __launch_bounds__(256) void wtransqkv_kernel(const float* __restrict__ wq,
                                                        const float* __restrict__ wk,
                                                        const float* __restrict__ wv,
                                                        fp16* __restrict__ T) {
    __shared__ float t[32][33];
    int z = blockIdx.z;
    int l = z / 3, which = z - l * 3;
    const float* W = (which == 0) ? wq : (which == 1) ? wk : wv;
    size_t inoff  = (size_t)l * D_ * D_;
    size_t outoff = (size_t)l * D3 * D_ + (size_t)which * D_ * D_;
    int k0 = blockIdx.y * 32, n0 = blockIdx.x * 32;
    int tx = threadIdx.x & 31, ty = threadIdx.x >> 5;
#pragma unroll
    for (int i = 0; i < 32; i += 8)
        t[ty + i][tx] = W[inoff + (size_t)(k0 + ty + i) * D_ + n0 + tx];
    __syncthreads();
#pragma unroll
    for (int i = 0; i < 32; i += 8)
        T[outoff + (size_t)(n0 + ty + i) * D_ + k0 + tx] = __float2half_rn(t[tx][ty + i]);
}

// ---------------- LayerNorm: fp32 in -> fp16 out ------------------------------
__global__ __launch_bounds__(256) void ln_kernel(const float* __restrict__ x,
                                                 const float* __restrict__ g,
                                                 const float* __restrict__ b,
                                                 fp16* __restrict__ y) {
    int row = blockIdx.x, tid = threadIdx.x;
    float4 f = *(const float4*)(x + (size_t)row * D_ + tid * 4);
    float s  = f.x + f.y + f.z + f.w;
    float ss = f.x*f.x + f.y*f.y + f.z*f.z + f.w*f.w;
#pragma unroll
    for (int o = 16; o > 0; o >>= 1) {
        s  += __shfl_xor_sync(0xffffffffu, s, o);
        ss += __shfl_xor_sync(0xffffffffu, ss, o);
    }
    __shared__ float rs[8], rss[8];
    if ((tid & 31) == 0) { rs[tid >> 5] = s; rss[tid >> 5] = ss; }
    __syncthreads();
    float ts = 0.f, tss = 0.f;
#pragma unroll
    for (int i = 0; i < 8; i++) { ts += rs[i]; tss += rss[i]; }
    float mean = ts * (1.0f / D_);
    float var  = tss * (1.0f / D_) - mean * mean;
    float r    = rsqrtf(var + 1e-6f);
    float4 g4 = *(const float4*)(g + tid * 4);
    float4 b4 = *(const float4*)(b + tid * 4);
    float o[4];
    o[0]=(f.x-mean)*r*g4.x+b4.x; o[1]=(f.y-mean)*r*g4.y+b4.y;
    o[2]=(f.z-mean)*r*g4.z+b4.z; o[3]=(f.w-mean)*r*g4.w+b4.w;
    size_t base = (size_t)row * D_ + tid * 4;
#pragma unroll
    for (int j = 0; j < 4; j += 2)
        *(__half2*)(y + base + j) = __halves2half2(__float2half_rn(o[j]), __float2half_rn(o[j+1]));
}

// ---------------- fp16 mma.sync GEMM 256x128, Kc=64, SW128, x4, 512 thr ------
// C = act(A@B^T + bias) + r1 + r2
static constexpr int A_TILE = 256 * 64 * 2;     // 32 KB
static constexpr int B_TILE = 128 * 64 * 2;     // 16 KB
static constexpr int S_A = 0, S_B = A_TILE;
static constexpr int STAGEB = A_TILE + B_TILE;  // 48 KB
static constexpr int GEMM_SMEM = 4 * STAGEB;    // 192 KB -> 1 CTA/SM

__device__ __forceinline__ void tileA_cpa(const fp16* __restrict__ g,
                                          int row0, int stride, int k0,
                                          uint32_t sdst, int tid) {
#pragma unroll
    for (int i = 0; i < 4; i++) {
        int idx = i * 512 + tid;
        int r = idx >> 3, c = idx & 7;
        CPA(sdst + swz(r * 128 + c * 16), g + (size_t)(row0 + r) * stride + k0 + c * 8);
    }
}
__device__ __forceinline__ void tileB_cpa(const fp16* __restrict__ g,
                                          int row0, int stride, int k0,
                                          uint32_t sdst, int tid) {
#pragma unroll
    for (int i = 0; i < 2; i++) {
        int idx = i * 512 + tid;
        int r = idx >> 3, c = idx & 7;
        CPA(sdst + swz(r * 128 + c * 16), g + (size_t)(row0 + r) * stride + k0 + c * 8);
    }
}

__global__ __launch_bounds__(512, 1) void gemm_mma_kernel(
    const fp16* __restrict__ A, const fp16* __restrict__ Bm,
    const float* __restrict__ bias, const float* __restrict__ r1,
    const float* __restrict__ r2, float* __restrict__ C,
    fp16* __restrict__ Ch, int NN, int KK, int act) {
    extern __shared__ char smem[];
    const uint32_t sb = smem_u32(smem);
    const int tid = threadIdx.x;
    const int wid = tid >> 5, lane = tid & 31;
    const int wm = wid >> 2, wn = wid & 3;
    const int rowBase = blockIdx.y * 256, colBase = blockIdx.x * 128;

    float acc[4][4][4];
#pragma unroll
    for (int i = 0; i < 4; i++)
#pragma unroll
        for (int j = 0; j < 4; j++)
#pragma unroll
            for (int q = 0; q < 4; q++) acc[i][j][q] = 0.f;

    const uint32_t a_row = (uint32_t)((wm * 64 + (lane & 15)) * 128);
    const uint32_t a_col = (uint32_t)((lane >> 4) * 16);
    const uint32_t b_row0 = (uint32_t)((wn * 32 + (lane & 7) + ((lane >> 4) << 3)) * 128);
    const uint32_t b_col = (uint32_t)(((lane >> 3) & 1) * 16);

    const int nc = KK / 64;
    // prologue: stages 0,1,2
#pragma unroll
    for (int p = 0; p < 3; p++) {
        uint32_t st = sb + p * STAGEB;
        tileA_cpa(A,  rowBase, KK, p * 64, st + S_A, tid);
        tileB_cpa(Bm, colBase, KK, p * 64, st + S_B, tid);
        CPA_COMMIT();
    }

    for (int c = 0; c < nc; c++) {
        int rem = nc - 1 - c;       // groups committed after chunk c's
        if (rem >= 2) CPA_WAIT2();
        else if (rem == 1) CPA_WAIT1();
        else CPA_WAIT0();
        __syncthreads();
        if (c + 3 < nc) {
            uint32_t st = sb + ((c + 3) & 3) * STAGEB;
            int k0 = (c + 3) * 64;
            tileA_cpa(A,  rowBase, KK, k0, st + S_A, tid);
            tileB_cpa(Bm, colBase, KK, k0, st + S_B, tid);
            CPA_COMMIT();
        }
        uint32_t st = sb + (c & 3) * STAGEB;

        // B fragments double-buffered across ks
        uint32_t bfr[2][2][4];
#pragma unroll
        for (int g = 0; g < 2; g++) {
            uint32_t roff = b_row0 + (uint32_t)(g * 16 * 128);
            ldsm4(bfr[0][g], st + S_B + smx(roff, b_col));
        }
#pragma unroll
        for (int ks = 0; ks < 4; ks++) {
            const int cur = ks & 1;
            if (ks < 3) {
                const uint32_t kbn = (ks + 1) * 32;
#pragma unroll
                for (int g = 0; g < 2; g++) {
                    uint32_t roff = b_row0 + (uint32_t)(g * 16 * 128);
                    ldsm4(bfr[cur ^ 1][g], st + S_B + smx(roff, kbn + b_col));
                }
            }
            const uint32_t kb = ks * 32;
#pragma unroll
            for (int mi = 0; mi < 4; mi++) {
                uint32_t roff = a_row + (uint32_t)(mi * 16 * 128);
                uint32_t af[4];
                ldsm4(af, st + S_A + smx(roff, kb + a_col));
#pragma unroll
                for (int nj = 0; nj < 4; nj++) {
                    int g = nj >> 1, o = (nj & 1) * 2;
                    mma16816h(acc[mi][nj], af, bfr[cur][g][o], bfr[cur][g][o + 1]);
                }
            }
        }
    }

    const int tq = lane >> 2, tr = lane & 3;
#pragma unroll
    for (int mi = 0; mi < 4; mi++) {
#pragma unroll
        for (int nj = 0; nj < 4; nj++) {
            int n = colBase + wn * 32 + nj * 8 + tr * 2;
            float2 bb = *(const float2*)(bias + n);
#pragma unroll
            for (int half = 0; half < 2; half++) {
                int m = rowBase + wm * 64 + mi * 16 + tq + half * 8;
                size_t base = (size_t)m * NN + n;
                float v0 = acc[mi][nj][half * 2 + 0] + bb.x;
                float v1 = acc[mi][nj][half * 2 + 1] + bb.y;
                if (act == 1) { v0 = v0 * normcdff(v0); v1 = v1 * normcdff(v1); }
                if (r1) { float2 q = *(const float2*)(r1 + base); v0 += q.x; v1 += q.y; }
                if (r2) { float2 q = *(const float2*)(r2 + base); v0 += q.x; v1 += q.y; }
                if (C) { float2 ov = {v0, v1}; *(float2*)(C + base) = ov; }
                if (Ch)
                    *(__half2*)(Ch + base) = __halves2half2(__float2half_rn(v0), __float2half_rn(v1));
            }
        }
    }
}

// ---------------- tensor-core attention (single-plane fp16) ------------------
static constexpr int QT = 32;
static constexpr int SCS2 = 520;
static constexpr int AO_Q  = 0;
static constexpr int AO_KV = 4096;
static constexpr int AO_SC = 20480;
static constexpr int AO_AW = 87040;
static constexpr int ATTN_SMEM = 120320;

__device__ __forceinline__ void tile64_cpa(const fp16* __restrict__ g,
                                           int row0, int stride, uint32_t sdst, int tid) {
#pragma unroll
    for (int i = 0; i < 2; i++) {
        int idx = i * 256 + tid;
        int r = idx >> 3, c = idx & 7;
        CPA(sdst + swz(r * 128 + c * 16), g + (size_t)(row0 + r) * stride + c * 8);
    }
}

__global__ __launch_bounds__(256, 1) void attn_mma_kernel(
    const fp16* __restrict__ qkv, const float* __restrict__ bias,
    fp16* __restrict__ Ctx) {
    extern __shared__ char smem[];
    const uint32_t sb = smem_u32(smem);
    const int tid = threadIdx.x;
    const int wid = tid >> 5, lane = tid & 31;
    const int wm = wid >> 2, wn = wid & 3;
    const int q0 = blockIdx.x * QT, h = blockIdx.y, b = blockIdx.z;
    const size_t base3 = (size_t)(b * S_) * D3 + h * DH_;
    const fp16* Q = qkv + base3;
    const fp16* K = qkv + base3 + D_;
    const fp16* V = qkv + base3 + 2 * D_;
    const int tq = lane >> 2, tr = lane & 3;

    {
        int r = tid >> 3, c = tid & 7;
        CPA(sb + AO_Q + swz(r * 128 + c * 16), Q + (size_t)(q0 + r) * D3 + c * 8);
    }
    tile64_cpa(K, 0, D3, sb + AO_KV, tid);
    CPA_COMMIT();
    CPA_WAIT0();
    __syncthreads();

    uint32_t qf[4][4];
    {
        uint32_t arow = (uint32_t)((wm * 16 + (lane & 15)) * 128);
        uint32_t acol = (uint32_t)((lane >> 4) * 16);
#pragma unroll
        for (int ks = 0; ks < 4; ks++)
            ldsm4(qf[ks], sb + AO_Q + smx(arow, ks * 32 + acol));
    }

    const uint32_t b_row = (uint32_t)((wn * 16 + (lane & 7) + ((lane >> 4) << 3)) * 128);
    const uint32_t b_col = (uint32_t)(((lane >> 3) & 1) * 16);
    for (int c = 0; c < 8; c++) {
        if (c < 7) {
            uint32_t st = sb + AO_KV + ((c + 1) & 1) * 8192;
            tile64_cpa(K, (c + 1) * 64, D3, st, tid);
            CPA_COMMIT();
            CPA_WAIT1();
        } else {
            CPA_WAIT0();
        }
        __syncthreads();
        uint32_t st = sb + AO_KV + (c & 1) * 8192;

        float acc[2][4] = {};
#pragma unroll
        for (int ks = 0; ks < 4; ks++) {
            uint32_t kh4[4];
            ldsm4(kh4, st + smx(b_row, ks * 32 + b_col));
#pragma unroll
            for (int nj = 0; nj < 2; nj++)
                mma16816h(acc[nj], qf[ks], kh4[nj * 2], kh4[nj * 2 + 1]);
        }
        float* sc = (float*)(smem + AO_SC);
#pragma unroll
        for (int nj = 0; nj < 2; nj++) {
            int kg = c * 64 + wn * 16 + nj * 8 + tr * 2;
#pragma unroll
            for (int half = 0; half < 2; half++) {
                int m = wm * 16 + tq + half * 8;
                int rel = (q0 + m) - kg + (P_ - 1);
                sc[m * SCS2 + kg]     = acc[nj][half*2+0] * 0.125f + __ldg(&bias[rel * H_ + h]);
                sc[m * SCS2 + kg + 1] = acc[nj][half*2+1] * 0.125f + __ldg(&bias[(rel - 1) * H_ + h]);
            }
        }
        __syncthreads();
    }

    tile64_cpa(V, 0, D3, sb + AO_KV, tid);
    CPA_COMMIT();

    {
        float* sc = (float*)(smem + AO_SC);
        fp16* aw = (fp16*)(smem + AO_AW);
#pragma unroll
        for (int rr = 0; rr < 4; rr++) {
            int r = wid * 4 + rr;
            float* row = sc + r * SCS2;
            float mx = -1e30f;
            for (int cc = lane; cc < S_; cc += 32) mx = fmaxf(mx, row[cc]);
#pragma unroll
            for (int o = 16; o > 0; o >>= 1) mx = fmaxf(mx, __shfl_xor_sync(0xffffffffu, mx, o));
            float sum = 0.f;
            for (int cc = lane; cc < S_; cc += 32) {
                float e = expf(row[cc] - mx);
                row[cc] = e;
                sum += e;
            }
#pragma unroll
            for (int o = 16; o > 0; o >>= 1) sum += __shfl_xor_sync(0xffffffffu, sum, o);
            float inv = 1.0f / sum;
            for (int cc = lane; cc < S_; cc += 32)
                aw[r * SCS2 + cc] = __float2half_rn(row[cc] * inv);
        }
    }
    __syncthreads();

    float cacc[2][4] = {};
    const uint32_t aw_row = (uint32_t)((wm * 16 + (lane & 15)) * (SCS2 * 2));
    const uint32_t v_row = (uint32_t)(((lane & 7) + ((lane >> 3) & 1) * 8) * 128);
    const uint32_t v_col = (uint32_t)(wn * 32 + (lane >> 4) * 16);
    for (int c = 0; c < 8; c++) {
        if (c < 7) {
            uint32_t st = sb + AO_KV + ((c + 1) & 1) * 8192;
            tile64_cpa(V, (c + 1) * 64, D3, st, tid);
            CPA_COMMIT();
            CPA_WAIT1();
        } else {
            CPA_WAIT0();
        }
        __syncthreads();
        uint32_t st = sb + AO_KV + (c & 1) * 8192;

#pragma unroll
        for (int ks = 0; ks < 4; ks++) {
            uint32_t awoff = aw_row + (uint32_t)((c * 64 + ks * 16 + (lane >> 4) * 8) * 2);
            uint32_t ah4[4];
            ldsm4(ah4, sb + AO_AW + awoff);
            uint32_t vh4[4];
            ldsm4t(vh4, st + smx(v_row + (uint32_t)(ks * 16 * 128), v_col));
#pragma unroll
            for (int nj = 0; nj < 2; nj++)
                mma16816h(cacc[nj], ah4, vh4[nj * 2], vh4[nj * 2 + 1]);
        }
        __syncthreads();
    }

#pragma unroll
    for (int nj = 0; nj < 2; nj++) {
        int n = wn * 16 + nj * 8 + tr * 2;
#pragma unroll
        for (int half = 0; half < 2; half++) {
            int m = wm * 16 + tq + half * 8;
            size_t gidx = (size_t)(b * S_ + q0 + m) * D_ + h * DH_ + n;
            *(__half2*)(Ctx + gidx) = __halves2half2(
                __float2half_rn(cacc[nj][half*2+0]), __float2half_rn(cacc[nj][half*2+1]));
        }
    }
}

// ---------------- launch ----------------------------------------------------
extern "C" void kernel_launch(void* const* d_in, const int* in_sizes, int n_in,
                              void* d_out, int out_size) {
    (void)in_sizes; (void)n_in; (void)out_size;
    const float* x    = (const float*)d_in[0];
    const float* pe   = (const float*)d_in[1];
    const float* wq   = (const float*)d_in[2];
    const float* bq   = (const float*)d_in[3];
    const float* wk   = (const float*)d_in[4];
    const float* bk   = (const float*)d_in[5];
    const float* wv   = (const float*)d_in[6];
    const float* bv   = (const float*)d_in[7];
    const float* wo   = (const float*)d_in[8];
    const float* bo   = (const float*)d_in[9];
    const float* bt   = (const float*)d_in[10];
    const float* w1   = (const float*)d_in[11];
    const float* b1   = (const float*)d_in[12];
    const float* w2   = (const float*)d_in[13];
    const float* b2   = (const float*)d_in[14];
    const float* ln1g = (const float*)d_in[15];
    const float* ln1b = (const float*)d_in[16];
    const float* ln2g = (const float*)d_in[17];
    const float* ln2b = (const float*)d_in[18];
    float* out = (float*)d_out;

    float *hb, *o1, *bqkv;
    fp16 *xn, *qkv, *cx, *f1, *wqkvp, *wop, *w1p, *w2p;
    cudaGetSymbolAddress((void**)&hb,   g_h);
    cudaGetSymbolAddress((void**)&o1,   g_out1);
    cudaGetSymbolAddress((void**)&bqkv, g_bqkv);
    cudaGetSymbolAddress((void**)&xn,   g_xn);
    cudaGetSymbolAddress((void**)&qkv,  g_qkv);
    cudaGetSymbolAddress((void**)&cx,   g_ctx);
    cudaGetSymbolAddress((void**)&f1,   g_f1);
    cudaGetSymbolAddress((void**)&wqkvp, g_wqkvT);
    cudaGetSymbolAddress((void**)&wop,  g_woT);
    cudaGetSymbolAddress((void**)&w1p,  g_w1T);
    cudaGetSymbolAddress((void**)&w2p,  g_w2T);

    cudaFuncSetAttribute(attn_mma_kernel, cudaFuncAttributeMaxDynamicSharedMemorySize, ATTN_SMEM);
    cudaFuncSetAttribute(gemm_mma_kernel, cudaFuncAttributeMaxDynamicSharedMemorySize, GEMM_SMEM);

    dim3 gQKV(D3 / 128, M_ / 256);
    dim3 gD(D_ / 128, M_ / 256);
    dim3 gF(F_ / 128, M_ / 256);
    dim3 gAttn(S_ / QT, H_, B_);

    addpe_kernel<<<(M_ * D_) / 256, 256>>>(x, pe, hb);
    packb_kernel<<<dim3(D_ / 256, L_), 256>>>(bq, bk, bv, bqkv);
    wtransqkv_kernel<<<dim3(32, 32, 3 * L_), 256>>>(wq, wk, wv, wqkvp);
    wtrans_kernel<<<dim3(32, 32, L_), 256>>>(wo, wop, D_, D_, (size_t)D_ * D_);
    wtrans_kernel<<<dim3(F_ / 32, D_ / 32, L_), 256>>>(w1, w1p, D_, F_, (size_t)D_ * F_);
    wtrans_kernel<<<dim3(D_ / 32, F_ / 32, L_), 256>>>(w2, w2p, F_, D_, (size_t)F_ * D_);

    for (int l = 0; l < L_; l++) {
        size_t oQKV = (size_t)l * D3 * D_;
        size_t oDD  = (size_t)l * D_ * D_;
        size_t oDF  = (size_t)l * D_ * F_;
        size_t oD   = (size_t)l * D_;
        size_t oF   = (size_t)l * F_;

        ln_kernel<<<M_, 256>>>(hb, ln1g + oD, ln1b + oD, xn);
        gemm_mma_kernel<<<gQKV, 512, GEMM_SMEM>>>(xn, wqkvp + oQKV,
            bqkv + (size_t)l * D3, nullptr, nullptr, nullptr, qkv, D3, D_, 0);

        attn_mma_kernel<<<gAttn, 256, ATTN_SMEM>>>(qkv,
            bt + (size_t)l * (2 * P_ - 1) * H_, cx);

        gemm_mma_kernel<<<gD, 512, GEMM_SMEM>>>(cx, wop + oDD,
            bo + oD, hb, nullptr, o1, nullptr, D_, D_, 0);

        ln_kernel<<<M_, 256>>>(o1, ln2g + oD, ln2b + oD, xn);
        gemm_mma_kernel<<<gF, 512, GEMM_SMEM>>>(xn, w1p + oDF,
            b1 + oF, nullptr, nullptr, nullptr, f1, F_, D_, 1);
        float* dst = (l == L_ - 1) ? out : hb;
        gemm_mma_kernel<<<gD, 512, GEMM_SMEM>>>(f1, w2p + oDF,
            b2 + oD, o1, hb, dst, nullptr, D_, F_, 0);
    }
}

// round 16
// speedup vs baseline: 1.0648x; 1.0648x over previous
#include <cuda_runtime.h>
#include <cuda_fp16.h>
#include <math.h>
#include <cstdint>

using fp16 = __half;

static constexpr int L_ = 6, D_ = 1024, H_ = 16, F_ = 4096, S_ = 512, B_ = 16, P_ = 512;
static constexpr int DH_ = D_ / H_;
static constexpr int M_ = B_ * S_;
static constexpr int D3 = 3 * D_;

// ---------------- scratch ----------------------------------------------------
__device__ __align__(16) float g_h[(size_t)M_ * D_];
__device__ __align__(16) float g_out1[(size_t)M_ * D_];

__device__ __align__(16) fp16 g_xn[(size_t)M_ * D_];
__device__ __align__(16) fp16 g_qkv[(size_t)M_ * D3];
__device__ __align__(16) fp16 g_ctx[(size_t)M_ * D_];
__device__ __align__(16) fp16 g_f1[(size_t)M_ * F_];

__device__ __align__(16) fp16 g_wqkvT[(size_t)L_ * D3 * D_];
__device__ __align__(16) fp16 g_woT[(size_t)L_ * D_ * D_];
__device__ __align__(16) fp16 g_w1T[(size_t)L_ * D_ * F_];
__device__ __align__(16) fp16 g_w2T[(size_t)L_ * F_ * D_];
__device__ __align__(16) float g_bqkv[(size_t)L_ * D3];

// ---------------- PTX helpers -------------------------------------------------
__device__ __forceinline__ uint32_t smem_u32(const void* p) {
    uint32_t a;
    asm("{ .reg .u64 t; cvta.to.shared.u64 t, %1; cvt.u32.u64 %0, t; }" : "=r"(a) : "l"(p));
    return a;
}
__device__ __forceinline__ void ldsm4(uint32_t* r, uint32_t addr) {
    asm volatile("ldmatrix.sync.aligned.m8n8.x4.shared.b16 {%0,%1,%2,%3}, [%4];"
                 : "=r"(r[0]), "=r"(r[1]), "=r"(r[2]), "=r"(r[3]) : "r"(addr));
}
__device__ __forceinline__ void ldsm4t(uint32_t* r, uint32_t addr) {
    asm volatile("ldmatrix.sync.aligned.m8n8.x4.trans.shared.b16 {%0,%1,%2,%3}, [%4];"
                 : "=r"(r[0]), "=r"(r[1]), "=r"(r[2]), "=r"(r[3]) : "r"(addr));
}
__device__ __forceinline__ void mma16816h(float* d, const uint32_t* a, uint32_t b0, uint32_t b1) {
    asm volatile("mma.sync.aligned.m16n8k16.row.col.f32.f16.f16.f32 "
                 "{%0,%1,%2,%3}, {%4,%5,%6,%7}, {%8,%9}, {%0,%1,%2,%3};"
                 : "+f"(d[0]), "+f"(d[1]), "+f"(d[2]), "+f"(d[3])
                 : "r"(a[0]), "r"(a[1]), "r"(a[2]), "r"(a[3]), "r"(b0), "r"(b1));
}
#define CPA(dst, src)  asm volatile("cp.async.cg.shared.global [%0], [%1], 16;" :: "r"(dst), "l"(src))
#define CPA_COMMIT()   asm volatile("cp.async.commit_group;" ::: "memory")
#define CPA_WAIT1()    asm volatile("cp.async.wait_group 1;" ::: "memory")
#define CPA_WAIT0()    asm volatile("cp.async.wait_group 0;" ::: "memory")

__device__ __forceinline__ uint32_t swz(uint32_t off) { return off ^ ((off >> 3) & 0x70); }
__device__ __forceinline__ uint32_t smx(uint32_t r, uint32_t c) { return r + (c ^ ((r >> 3) & 0x70)); }

// ---------------- h = x + pe -------------------------------------------------
__global__ __launch_bounds__(256) void addpe_kernel(const float* __restrict__ x,
                                                    const float* __restrict__ pe,
                                                    float* __restrict__ h) {
    int i = blockIdx.x * 256 + threadIdx.x;
    h[i] = x[i] + pe[i & (S_ * D_ - 1)];
}

// ---------------- pack qkv bias ----------------------------------------------
__global__ __launch_bounds__(256) void packb_kernel(const float* __restrict__ bq,
                                                    const float* __restrict__ bk,
                                                    const float* __restrict__ bv,
                                                    float* __restrict__ o) {
    int l = blockIdx.y;
    int i = blockIdx.x * 256 + threadIdx.x;
    o[(size_t)l * D3 + i]          = bq[l * D_ + i];
    o[(size_t)l * D3 + D_ + i]     = bk[l * D_ + i];
    o[(size_t)l * D3 + 2 * D_ + i] = bv[l * D_ + i];
}

// ---------------- weight transpose: W[K,N] -> T[N,K] fp16 --------------------
__global__ __launch_bounds__(256) void wtrans_kernel(const float* __restrict__ W,
                                                     fp16* __restrict__ T,
                                                     int K, int N, size_t out_ls) {
    __shared__ float t[32][33];
    size_t inoff  = (size_t)blockIdx.z * K * N;
    size_t outoff = (size_t)blockIdx.z * out_ls;
    int k0 = blockIdx.y * 32, n0 = blockIdx.x * 32;
    int tx = threadIdx.x & 31, ty = threadIdx.x >> 5;
#pragma unroll
    for (int i = 0; i < 32; i += 8)
        t[ty + i][tx] = W[inoff + (size_t)(k0 + ty + i) * N + n0 + tx];
    __syncthreads();
#pragma unroll
    for (int i = 0; i < 32; i += 8)
        T[outoff + (size_t)(n0 + ty + i) * K + k0 + tx] = __float2half_rn(t[tx][ty + i]);
}

// merged q/k/v transpose -> fused [D3,K] fp16
__global__ __launch_bounds__(256) void wtransqkv_kernel(const float* __restrict__ wq,
                                                        const float* __restrict__ wk,
                                                        const float* __restrict__ wv,
                                                        fp16* __restrict__ T) {
    __shared__ float t[32][33];
    int z = blockIdx.z;
    int l = z / 3, which = z - l * 3;
    const float* W = (which == 0) ? wq : (which == 1) ? wk : wv;
    size_t inoff  = (size_t)l * D_ * D_;
    size_t outoff = (size_t)l * D3 * D_ + (size_t)which * D_ * D_;
    int k0 = blockIdx.y * 32, n0 = blockIdx.x * 32;
    int tx = threadIdx.x & 31, ty = threadIdx.x >> 5;
#pragma unroll
    for (int i = 0; i < 32; i += 8)
        t[ty + i][tx] = W[inoff + (size_t)(k0 + ty + i) * D_ + n0 + tx];
    __syncthreads();
#pragma unroll
    for (int i = 0; i < 32; i += 8)
        T[outoff + (size_t)(n0 + ty + i) * D_ + k0 + tx] = __float2half_rn(t[tx][ty + i]);
}

// ---------------- LayerNorm: fp32 in -> fp16 out ------------------------------
__global__ __launch_bounds__(256) void ln_kernel(const float* __restrict__ x,
                                                 const float* __restrict__ g,
                                                 const float* __restrict__ b,
                                                 fp16* __restrict__ y) {
    int row = blockIdx.x, tid = threadIdx.x;
    float4 f = *(const float4*)(x + (size_t)row * D_ + tid * 4);
    float s  = f.x + f.y + f.z + f.w;
    float ss = f.x*f.x + f.y*f.y + f.z*f.z + f.w*f.w;
#pragma unroll
    for (int o = 16; o > 0; o >>= 1) {
        s  += __shfl_xor_sync(0xffffffffu, s, o);
        ss += __shfl_xor_sync(0xffffffffu, ss, o);
    }
    __shared__ float rs[8], rss[8];
    if ((tid & 31) == 0) { rs[tid >> 5] = s; rss[tid >> 5] = ss; }
    __syncthreads();
    float ts = 0.f, tss = 0.f;
#pragma unroll
    for (int i = 0; i < 8; i++) { ts += rs[i]; tss += rss[i]; }
    float mean = ts * (1.0f / D_);
    float var  = tss * (1.0f / D_) - mean * mean;
    float r    = rsqrtf(var + 1e-6f);
    float4 g4 = *(const float4*)(g + tid * 4);
    float4 b4 = *(const float4*)(b + tid * 4);
    float o[4];
    o[0]=(f.x-mean)*r*g4.x+b4.x; o[1]=(f.y-mean)*r*g4.y+b4.y;
    o[2]=(f.z-mean)*r*g4.z+b4.z; o[3]=(f.w-mean)*r*g4.w+b4.w;
    size_t base = (size_t)row * D_ + tid * 4;
#pragma unroll
    for (int j = 0; j < 4; j += 2)
        *(__half2*)(y + base + j) = __halves2half2(__float2half_rn(o[j]), __float2half_rn(o[j+1]));
}

// ---------------- fp16 mma.sync GEMM 256x128, Kc=64, SW128, x3, 512 thr ------
// (R14 configuration — best measured)
static constexpr int A_TILE = 256 * 64 * 2;     // 32 KB
static constexpr int B_TILE = 128 * 64 * 2;     // 16 KB
static constexpr int S_A = 0, S_B = A_TILE;
static constexpr int STAGEB = A_TILE + B_TILE;  // 48 KB
static constexpr int GEMM_SMEM = 3 * STAGEB;    // 144 KB -> 1 CTA/SM

__device__ __forceinline__ void tileA_cpa(const fp16* __restrict__ g,
                                          int row0, int stride, int k0,
                                          uint32_t sdst, int tid) {
#pragma unroll
    for (int i = 0; i < 4; i++) {
        int idx = i * 512 + tid;
        int r = idx >> 3, c = idx & 7;
        CPA(sdst + swz(r * 128 + c * 16), g + (size_t)(row0 + r) * stride + k0 + c * 8);
    }
}
__device__ __forceinline__ void tileB_cpa(const fp16* __restrict__ g,
                                          int row0, int stride, int k0,
                                          uint32_t sdst, int tid) {
#pragma unroll
    for (int i = 0; i < 2; i++) {
        int idx = i * 512 + tid;
        int r = idx >> 3, c = idx & 7;
        CPA(sdst + swz(r * 128 + c * 16), g + (size_t)(row0 + r) * stride + k0 + c * 8);
    }
}

__global__ __launch_bounds__(512, 1) void gemm_mma_kernel(
    const fp16* __restrict__ A, const fp16* __restrict__ Bm,
    const float* __restrict__ bias, const float* __restrict__ r1,
    const float* __restrict__ r2, float* __restrict__ C,
    fp16* __restrict__ Ch, int NN, int KK, int act) {
    extern __shared__ char smem[];
    const uint32_t sb = smem_u32(smem);
    const int tid = threadIdx.x;
    const int wid = tid >> 5, lane = tid & 31;
    const int wm = wid >> 2, wn = wid & 3;
    const int rowBase = blockIdx.y * 256, colBase = blockIdx.x * 128;

    float acc[4][4][4];
#pragma unroll
    for (int i = 0; i < 4; i++)
#pragma unroll
        for (int j = 0; j < 4; j++)
#pragma unroll
            for (int q = 0; q < 4; q++) acc[i][j][q] = 0.f;

    const uint32_t a_row = (uint32_t)((wm * 64 + (lane & 15)) * 128);
    const uint32_t a_col = (uint32_t)((lane >> 4) * 16);
    const uint32_t b_row0 = (uint32_t)((wn * 32 + (lane & 7) + ((lane >> 4) << 3)) * 128);
    const uint32_t b_col = (uint32_t)(((lane >> 3) & 1) * 16);

    const int nc = KK / 64;
    tileA_cpa(A,  rowBase, KK, 0, sb + S_A, tid);
    tileB_cpa(Bm, colBase, KK, 0, sb + S_B, tid);
    CPA_COMMIT();
    {
        uint32_t st = sb + STAGEB;
        tileA_cpa(A,  rowBase, KK, 64, st + S_A, tid);
        tileB_cpa(Bm, colBase, KK, 64, st + S_B, tid);
    }
    CPA_COMMIT();

    for (int c = 0; c < nc; c++) {
        if (c + 1 < nc) CPA_WAIT1(); else CPA_WAIT0();
        __syncthreads();
        if (c + 2 < nc) {
            uint32_t st = sb + ((c + 2) % 3) * STAGEB;
            int k0 = (c + 2) * 64;
            tileA_cpa(A,  rowBase, KK, k0, st + S_A, tid);
            tileB_cpa(Bm, colBase, KK, k0, st + S_B, tid);
            CPA_COMMIT();
        }
        uint32_t st = sb + (c % 3) * STAGEB;

#pragma unroll
        for (int ks = 0; ks < 4; ks++) {
            const uint32_t kb = ks * 32;
            uint32_t bh[2][4];
#pragma unroll
            for (int g = 0; g < 2; g++) {
                uint32_t roff = b_row0 + (uint32_t)(g * 16 * 128);
                ldsm4(bh[g], st + S_B + smx(roff, kb + b_col));
            }
#pragma unroll
            for (int mi = 0; mi < 4; mi++) {
                uint32_t roff = a_row + (uint32_t)(mi * 16 * 128);
                uint32_t af[4];
                ldsm4(af, st + S_A + smx(roff, kb + a_col));
#pragma unroll
                for (int nj = 0; nj < 4; nj++) {
                    int g = nj >> 1, o = (nj & 1) * 2;
                    mma16816h(acc[mi][nj], af, bh[g][o], bh[g][o + 1]);
                }
            }
        }
    }

    const int tq = lane >> 2, tr = lane & 3;
#pragma unroll
    for (int mi = 0; mi < 4; mi++) {
#pragma unroll
        for (int nj = 0; nj < 4; nj++) {
            int n = colBase + wn * 32 + nj * 8 + tr * 2;
            float2 bb = *(const float2*)(bias + n);
#pragma unroll
            for (int half = 0; half < 2; half++) {
                int m = rowBase + wm * 64 + mi * 16 + tq + half * 8;
                size_t base = (size_t)m * NN + n;
                float v0 = acc[mi][nj][half * 2 + 0] + bb.x;
                float v1 = acc[mi][nj][half * 2 + 1] + bb.y;
                if (act == 1) { v0 = v0 * normcdff(v0); v1 = v1 * normcdff(v1); }
                if (r1) { float2 q = *(const float2*)(r1 + base); v0 += q.x; v1 += q.y; }
                if (r2) { float2 q = *(const float2*)(r2 + base); v0 += q.x; v1 += q.y; }
                if (C) { float2 ov = {v0, v1}; *(float2*)(C + base) = ov; }
                if (Ch)
                    *(__half2*)(Ch + base) = __halves2half2(__float2half_rn(v0), __float2half_rn(v1));
            }
        }
    }
}

// ---------------- tensor-core attention (QT=64, single-plane fp16) -----------
static constexpr int QT = 64;
static constexpr int SCS2 = 520;
static constexpr int AO_Q  = 0;                         // 64x128B = 8192
static constexpr int AO_KV = 8192;                      // 2 stages x 8192
static constexpr int AO_SC = 24576;                     // 64*520*4 = 133120
static constexpr int AO_AW = 157696;                    // 64*520*2 = 66560
static constexpr int ATTN_SMEM = 224256;

__device__ __forceinline__ void tile64_cpa(const fp16* __restrict__ g,
                                           int row0, int stride, uint32_t sdst, int tid) {
#pragma unroll
    for (int i = 0; i < 2; i++) {
        int idx = i * 256 + tid;
        int r = idx >> 3, c = idx & 7;
        CPA(sdst + swz(r * 128 + c * 16), g + (size_t)(row0 + r) * stride + c * 8);
    }
}

__global__ __launch_bounds__(256, 1) void attn_mma_kernel(
    const fp16* __restrict__ qkv, const float* __restrict__ bias,
    fp16* __restrict__ Ctx) {
    extern __shared__ char smem[];
    const uint32_t sb = smem_u32(smem);
    const int tid = threadIdx.x;
    const int wid = tid >> 5, lane = tid & 31;
    const int wm = wid >> 2, wn = wid & 3;
    const int q0 = blockIdx.x * QT, h = blockIdx.y, b = blockIdx.z;
    const size_t base3 = (size_t)(b * S_) * D3 + h * DH_;
    const fp16* Q = qkv + base3;
    const fp16* K = qkv + base3 + D_;
    const fp16* V = qkv + base3 + 2 * D_;
    const int tq = lane >> 2, tr = lane & 3;

    // Q tile 64x64 fp16 = 64 rows x 128 B
    {
#pragma unroll
        for (int i = 0; i < 2; i++) {
            int idx = i * 256 + tid;
            int r = idx >> 3, c = idx & 7;
            CPA(sb + AO_Q + swz(r * 128 + c * 16), Q + (size_t)(q0 + r) * D3 + c * 8);
        }
    }
    tile64_cpa(K, 0, D3, sb + AO_KV, tid);
    CPA_COMMIT();
    CPA_WAIT0();
    __syncthreads();

    uint32_t qf[2][4][4];
    {
        uint32_t acol = (uint32_t)((lane >> 4) * 16);
#pragma unroll
        for (int mi = 0; mi < 2; mi++) {
            uint32_t arow = (uint32_t)((wm * 32 + mi * 16 + (lane & 15)) * 128);
#pragma unroll
            for (int ks = 0; ks < 4; ks++)
                ldsm4(qf[mi][ks], sb + AO_Q + smx(arow, ks * 32 + acol));
        }
    }

    const uint32_t b_row = (uint32_t)((wn * 16 + (lane & 7) + ((lane >> 4) << 3)) * 128);
    const uint32_t b_col = (uint32_t)(((lane >> 3) & 1) * 16);
    for (int c = 0; c < 8; c++) {
        if (c < 7) {
            uint32_t st = sb + AO_KV + ((c + 1) & 1) * 8192;
            tile64_cpa(K, (c + 1) * 64, D3, st, tid);
            CPA_COMMIT();
            CPA_WAIT1();
        } else {
            CPA_WAIT0();
        }
        __syncthreads();
        uint32_t st = sb + AO_KV + (c & 1) * 8192;

        float acc[2][2][4] = {};
#pragma unroll
        for (int ks = 0; ks < 4; ks++) {
            uint32_t kh4[4];
            ldsm4(kh4, st + smx(b_row, ks * 32 + b_col));
#pragma unroll
            for (int mi = 0; mi < 2; mi++)
#pragma unroll
                for (int nj = 0; nj < 2; nj++)
                    mma16816h(acc[mi][nj], qf[mi][ks], kh4[nj * 2], kh4[nj * 2 + 1]);
        }
        float* sc = (float*)(smem + AO_SC);
#pragma unroll
        for (int mi = 0; mi < 2; mi++) {
#pragma unroll
            for (int nj = 0; nj < 2; nj++) {
                int kg = c * 64 + wn * 16 + nj * 8 + tr * 2;
#pragma unroll
                for (int half = 0; half < 2; half++) {
                    int m = wm * 32 + mi * 16 + tq + half * 8;
                    int rel = (q0 + m) - kg + (P_ - 1);
                    sc[m * SCS2 + kg]     = acc[mi][nj][half*2+0] * 0.125f + __ldg(&bias[rel * H_ + h]);
                    sc[m * SCS2 + kg + 1] = acc[mi][nj][half*2+1] * 0.125f + __ldg(&bias[(rel - 1) * H_ + h]);
                }
            }
        }
        __syncthreads();
    }

    tile64_cpa(V, 0, D3, sb + AO_KV, tid);
    CPA_COMMIT();

    {
        float* sc = (float*)(smem + AO_SC);
        fp16* aw = (fp16*)(smem + AO_AW);
#pragma unroll
        for (int rr = 0; rr < 8; rr++) {
            int r = wid * 8 + rr;
            float* row = sc + r * SCS2;
            float mx = -1e30f;
            for (int cc = lane; cc < S_; cc += 32) mx = fmaxf(mx, row[cc]);
#pragma unroll
            for (int o = 16; o > 0; o >>= 1) mx = fmaxf(mx, __shfl_xor_sync(0xffffffffu, mx, o));
            float sum = 0.f;
            for (int cc = lane; cc < S_; cc += 32) {
                float e = expf(row[cc] - mx);
                row[cc] = e;
                sum += e;
            }
#pragma unroll
            for (int o = 16; o > 0; o >>= 1) sum += __shfl_xor_sync(0xffffffffu, sum, o);
            float inv = 1.0f / sum;
            for (int cc = lane; cc < S_; cc += 32)
                aw[r * SCS2 + cc] = __float2half_rn(row[cc] * inv);
        }
    }
    __syncthreads();

    float cacc[2][2][4] = {};
    const uint32_t v_row = (uint32_t)(((lane & 7) + ((lane >> 3) & 1) * 8) * 128);
    const uint32_t v_col = (uint32_t)(wn * 32 + (lane >> 4) * 16);
    for (int c = 0; c < 8; c++) {
        if (c < 7) {
            uint32_t st = sb + AO_KV + ((c + 1) & 1) * 8192;
            tile64_cpa(V, (c + 1) * 64, D3, st, tid);
            CPA_COMMIT();
            CPA_WAIT1();
        } else {
            CPA_WAIT0();
        }
        __syncthreads();
        uint32_t st = sb + AO_KV + (c & 1) * 8192;

#pragma unroll
        for (int ks = 0; ks < 4; ks++) {
            uint32_t vh4[4];
            ldsm4t(vh4, st + smx(v_row + (uint32_t)(ks * 16 * 128), v_col));
#pragma unroll
            for (int mi = 0; mi < 2; mi++) {
                uint32_t aw_row = (uint32_t)((wm * 32 + mi * 16 + (lane & 15)) * (SCS2 * 2));
                uint32_t awoff = aw_row + (uint32_t)((c * 64 + ks * 16 + (lane >> 4) * 8) * 2);
                uint32_t ah4[4];
                ldsm4(ah4, sb + AO_AW + awoff);
#pragma unroll
                for (int nj = 0; nj < 2; nj++)
                    mma16816h(cacc[mi][nj], ah4, vh4[nj * 2], vh4[nj * 2 + 1]);
            }
        }
        __syncthreads();
    }

#pragma unroll
    for (int mi = 0; mi < 2; mi++) {
#pragma unroll
        for (int nj = 0; nj < 2; nj++) {
            int n = wn * 16 + nj * 8 + tr * 2;
#pragma unroll
            for (int half = 0; half < 2; half++) {
                int m = wm * 32 + mi * 16 + tq + half * 8;
                size_t gidx = (size_t)(b * S_ + q0 + m) * D_ + h * DH_ + n;
                *(__half2*)(Ctx + gidx) = __halves2half2(
                    __float2half_rn(cacc[mi][nj][half*2+0]), __float2half_rn(cacc[mi][nj][half*2+1]));
            }
        }
    }
}

// ---------------- launch ----------------------------------------------------
extern "C" void kernel_launch(void* const* d_in, const int* in_sizes, int n_in,
                              void* d_out, int out_size) {
    (void)in_sizes; (void)n_in; (void)out_size;
    const float* x    = (const float*)d_in[0];
    const float* pe   = (const float*)d_in[1];
    const float* wq   = (const float*)d_in[2];
    const float* bq   = (const float*)d_in[3];
    const float* wk   = (const float*)d_in[4];
    const float* bk   = (const float*)d_in[5];
    const float* wv   = (const float*)d_in[6];
    const float* bv   = (const float*)d_in[7];
    const float* wo   = (const float*)d_in[8];
    const float* bo   = (const float*)d_in[9];
    const float* bt   = (const float*)d_in[10];
    const float* w1   = (const float*)d_in[11];
    const float* b1   = (const float*)d_in[12];
    const float* w2   = (const float*)d_in[13];
    const float* b2   = (const float*)d_in[14];
    const float* ln1g = (const float*)d_in[15];
    const float* ln1b = (const float*)d_in[16];
    const float* ln2g = (const float*)d_in[17];
    const float* ln2b = (const float*)d_in[18];
    float* out = (float*)d_out;

    float *hb, *o1, *bqkv;
    fp16 *xn, *qkv, *cx, *f1, *wqkvp, *wop, *w1p, *w2p;
    cudaGetSymbolAddress((void**)&hb,   g_h);
    cudaGetSymbolAddress((void**)&o1,   g_out1);
    cudaGetSymbolAddress((void**)&bqkv, g_bqkv);
    cudaGetSymbolAddress((void**)&xn,   g_xn);
    cudaGetSymbolAddress((void**)&qkv,  g_qkv);
    cudaGetSymbolAddress((void**)&cx,   g_ctx);
    cudaGetSymbolAddress((void**)&f1,   g_f1);
    cudaGetSymbolAddress((void**)&wqkvp, g_wqkvT);
    cudaGetSymbolAddress((void**)&wop,  g_woT);
    cudaGetSymbolAddress((void**)&w1p,  g_w1T);
    cudaGetSymbolAddress((void**)&w2p,  g_w2T);

    cudaFuncSetAttribute(attn_mma_kernel, cudaFuncAttributeMaxDynamicSharedMemorySize, ATTN_SMEM);
    cudaFuncSetAttribute(gemm_mma_kernel, cudaFuncAttributeMaxDynamicSharedMemorySize, GEMM_SMEM);

    dim3 gQKV(D3 / 128, M_ / 256);
    dim3 gD(D_ / 128, M_ / 256);
    dim3 gF(F_ / 128, M_ / 256);
    dim3 gAttn(S_ / QT, H_, B_);   // (8, 16, 16)

    addpe_kernel<<<(M_ * D_) / 256, 256>>>(x, pe, hb);
    packb_kernel<<<dim3(D_ / 256, L_), 256>>>(bq, bk, bv, bqkv);
    wtransqkv_kernel<<<dim3(32, 32, 3 * L_), 256>>>(wq, wk, wv, wqkvp);
    wtrans_kernel<<<dim3(32, 32, L_), 256>>>(wo, wop, D_, D_, (size_t)D_ * D_);
    wtrans_kernel<<<dim3(F_ / 32, D_ / 32, L_), 256>>>(w1, w1p, D_, F_, (size_t)D_ * F_);
    wtrans_kernel<<<dim3(D_ / 32, F_ / 32, L_), 256>>>(w2, w2p, F_, D_, (size_t)F_ * D_);

    for (int l = 0; l < L_; l++) {
        size_t oQKV = (size_t)l * D3 * D_;
        size_t oDD  = (size_t)l * D_ * D_;
        size_t oDF  = (size_t)l * D_ * F_;
        size_t oD   = (size_t)l * D_;
        size_t oF   = (size_t)l * F_;

        ln_kernel<<<M_, 256>>>(hb, ln1g + oD, ln1b + oD, xn);
        gemm_mma_kernel<<<gQKV, 512, GEMM_SMEM>>>(xn, wqkvp + oQKV,
            bqkv + (size_t)l * D3, nullptr, nullptr, nullptr, qkv, D3, D_, 0);

        attn_mma_kernel<<<gAttn, 256, ATTN_SMEM>>>(qkv,
            bt + (size_t)l * (2 * P_ - 1) * H_, cx);

        gemm_mma_kernel<<<gD, 512, GEMM_SMEM>>>(cx, wop + oDD,
            bo + oD, hb, nullptr, o1, nullptr, D_, D_, 0);

        ln_kernel<<<M_, 256>>>(o1, ln2g + oD, ln2b + oD, xn);
        gemm_mma_kernel<<<gF, 512, GEMM_SMEM>>>(xn, w1p + oDF,
            b1 + oF, nullptr, nullptr, nullptr, f1, F_, D_, 1);
        float* dst = (l == L_ - 1) ? out : hb;
        gemm_mma_kernel<<<gD, 512, GEMM_SMEM>>>(f1, w2p + oDF,
            b2 + oD, o1, hb, dst, nullptr, D_, F_, 0);
    }
}

// round 17
// speedup vs baseline: 1.1606x; 1.0900x over previous
#include <cuda_runtime.h>
#include <cuda_fp16.h>
#include <math.h>
#include <cstdint>

using fp16 = __half;

static constexpr int L_ = 6, D_ = 1024, H_ = 16, F_ = 4096, S_ = 512, B_ = 16, P_ = 512;
static constexpr int DH_ = D_ / H_;
static constexpr int M_ = B_ * S_;
static constexpr int D3 = 3 * D_;

// ---------------- scratch ----------------------------------------------------
__device__ __align__(16) float g_h[(size_t)M_ * D_];
__device__ __align__(16) float g_out1[(size_t)M_ * D_];

__device__ __align__(16) fp16 g_xn[(size_t)M_ * D_];
__device__ __align__(16) fp16 g_qkv[(size_t)M_ * D3];
__device__ __align__(16) fp16 g_ctx[(size_t)M_ * D_];
__device__ __align__(16) fp16 g_f1[(size_t)M_ * F_];

__device__ __align__(16) fp16 g_wqkvT[(size_t)L_ * D3 * D_];
__device__ __align__(16) fp16 g_woT[(size_t)L_ * D_ * D_];
__device__ __align__(16) fp16 g_w1T[(size_t)L_ * D_ * F_];
__device__ __align__(16) fp16 g_w2T[(size_t)L_ * F_ * D_];
__device__ __align__(16) float g_bqkv[(size_t)L_ * D3];

// ---------------- PTX helpers -------------------------------------------------
__device__ __forceinline__ uint32_t smem_u32(const void* p) {
    uint32_t a;
    asm("{ .reg .u64 t; cvta.to.shared.u64 t, %1; cvt.u32.u64 %0, t; }" : "=r"(a) : "l"(p));
    return a;
}
__device__ __forceinline__ void ldsm4(uint32_t* r, uint32_t addr) {
    asm volatile("ldmatrix.sync.aligned.m8n8.x4.shared.b16 {%0,%1,%2,%3}, [%4];"
                 : "=r"(r[0]), "=r"(r[1]), "=r"(r[2]), "=r"(r[3]) : "r"(addr));
}
__device__ __forceinline__ void ldsm4t(uint32_t* r, uint32_t addr) {
    asm volatile("ldmatrix.sync.aligned.m8n8.x4.trans.shared.b16 {%0,%1,%2,%3}, [%4];"
                 : "=r"(r[0]), "=r"(r[1]), "=r"(r[2]), "=r"(r[3]) : "r"(addr));
}
__device__ __forceinline__ void mma16816h(float* d, const uint32_t* a, uint32_t b0, uint32_t b1) {
    asm volatile("mma.sync.aligned.m16n8k16.row.col.f32.f16.f16.f32 "
                 "{%0,%1,%2,%3}, {%4,%5,%6,%7}, {%8,%9}, {%0,%1,%2,%3};"
                 : "+f"(d[0]), "+f"(d[1]), "+f"(d[2]), "+f"(d[3])
                 : "r"(a[0]), "r"(a[1]), "r"(a[2]), "r"(a[3]), "r"(b0), "r"(b1));
}
#define CPA(dst, src)  asm volatile("cp.async.cg.shared.global [%0], [%1], 16;" :: "r"(dst), "l"(src))
#define CPA_COMMIT()   asm volatile("cp.async.commit_group;" ::: "memory")
#define CPA_WAIT1()    asm volatile("cp.async.wait_group 1;" ::: "memory")
#define CPA_WAIT0()    asm volatile("cp.async.wait_group 0;" ::: "memory")

__device__ __forceinline__ uint32_t swz(uint32_t off) { return off ^ ((off >> 3) & 0x70); }
__device__ __forceinline__ uint32_t smx(uint32_t r, uint32_t c) { return r + (c ^ ((r >> 3) & 0x70)); }

// ---------------- pack qkv bias ----------------------------------------------
__global__ __launch_bounds__(256) void packb_kernel(const float* __restrict__ bq,
                                                    const float* __restrict__ bk,
                                                    const float* __restrict__ bv,
                                                    float* __restrict__ o) {
    int l = blockIdx.y;
    int i = blockIdx.x * 256 + threadIdx.x;
    o[(size_t)l * D3 + i]          = bq[l * D_ + i];
    o[(size_t)l * D3 + D_ + i]     = bk[l * D_ + i];
    o[(size_t)l * D3 + 2 * D_ + i] = bv[l * D_ + i];
}

// ---------------- weight transpose: W[K,N] -> T[N,K] fp16 --------------------
__global__ __launch_bounds__(256) void wtrans_kernel(const float* __restrict__ W,
                                                     fp16* __restrict__ T,
                                                     int K, int N, size_t out_ls) {
    __shared__ float t[32][33];
    size_t inoff  = (size_t)blockIdx.z * K * N;
    size_t outoff = (size_t)blockIdx.z * out_ls;
    int k0 = blockIdx.y * 32, n0 = blockIdx.x * 32;
    int tx = threadIdx.x & 31, ty = threadIdx.x >> 5;
#pragma unroll
    for (int i = 0; i < 32; i += 8)
        t[ty + i][tx] = W[inoff + (size_t)(k0 + ty + i) * N + n0 + tx];
    __syncthreads();
#pragma unroll
    for (int i = 0; i < 32; i += 8)
        T[outoff + (size_t)(n0 + ty + i) * K + k0 + tx] = __float2half_rn(t[tx][ty + i]);
}

// merged q/k/v transpose -> fused [D3,K] fp16
__global__ __launch_bounds__(256) void wtransqkv_kernel(const float* __restrict__ wq,
                                                        const float* __restrict__ wk,
                                                        const float* __restrict__ wv,
                                                        fp16* __restrict__ T) {
    __shared__ float t[32][33];
    int z = blockIdx.z;
    int l = z / 3, which = z - l * 3;
    const float* W = (which == 0) ? wq : (which == 1) ? wk : wv;
    size_t inoff  = (size_t)l * D_ * D_;
    size_t outoff = (size_t)l * D3 * D_ + (size_t)which * D_ * D_;
    int k0 = blockIdx.y * 32, n0 = blockIdx.x * 32;
    int tx = threadIdx.x & 31, ty = threadIdx.x >> 5;
#pragma unroll
    for (int i = 0; i < 32; i += 8)
        t[ty + i][tx] = W[inoff + (size_t)(k0 + ty + i) * D_ + n0 + tx];
    __syncthreads();
#pragma unroll
    for (int i = 0; i < 32; i += 8)
        T[outoff + (size_t)(n0 + ty + i) * D_ + k0 + tx] = __float2half_rn(t[tx][ty + i]);
}

// ---------------- LayerNorm cores ---------------------------------------------
__device__ __forceinline__ void ln_core(float* o, float4 f, const float* g,
                                        const float* b, int tid) {
    float s  = f.x + f.y + f.z + f.w;
    float ss = f.x*f.x + f.y*f.y + f.z*f.z + f.w*f.w;
#pragma unroll
    for (int off = 16; off > 0; off >>= 1) {
        s  += __shfl_xor_sync(0xffffffffu, s, off);
        ss += __shfl_xor_sync(0xffffffffu, ss, off);
    }
    __shared__ float rs[8], rss[8];
    if ((tid & 31) == 0) { rs[tid >> 5] = s; rss[tid >> 5] = ss; }
    __syncthreads();
    float ts = 0.f, tss = 0.f;
#pragma unroll
    for (int i = 0; i < 8; i++) { ts += rs[i]; tss += rss[i]; }
    float mean = ts * (1.0f / D_);
    float var  = tss * (1.0f / D_) - mean * mean;
    float r    = rsqrtf(var + 1e-6f);
    float4 g4 = *(const float4*)(g + tid * 4);
    float4 b4 = *(const float4*)(b + tid * 4);
    o[0] = (f.x - mean) * r * g4.x + b4.x;
    o[1] = (f.y - mean) * r * g4.y + b4.y;
    o[2] = (f.z - mean) * r * g4.z + b4.z;
    o[3] = (f.w - mean) * r * g4.w + b4.w;
}

// LN: fp32 in -> fp16 out
__global__ __launch_bounds__(256) void ln_kernel(const float* __restrict__ x,
                                                 const float* __restrict__ g,
                                                 const float* __restrict__ b,
                                                 fp16* __restrict__ y) {
    int row = blockIdx.x, tid = threadIdx.x;
    float4 f = *(const float4*)(x + (size_t)row * D_ + tid * 4);
    float o[4];
    ln_core(o, f, g, b, tid);
    size_t base = (size_t)row * D_ + tid * 4;
#pragma unroll
    for (int j = 0; j < 4; j += 2)
        *(__half2*)(y + base + j) = __halves2half2(__float2half_rn(o[j]), __float2half_rn(o[j+1]));
}

// layer-0 fused: h = x + pe (write fp32) ; y = LN(h) fp16
__global__ __launch_bounds__(256) void ln0_kernel(const float* __restrict__ x,
                                                  const float* __restrict__ pe,
                                                  const float* __restrict__ g,
                                                  const float* __restrict__ b,
                                                  float* __restrict__ hb,
                                                  fp16* __restrict__ y) {
    int row = blockIdx.x, tid = threadIdx.x;
    size_t base = (size_t)row * D_ + tid * 4;
    float4 xv = *(const float4*)(x + base);
    float4 pv = *(const float4*)(pe + ((base) & (size_t)(S_ * D_ - 1)));
    float4 f = {xv.x + pv.x, xv.y + pv.y, xv.z + pv.z, xv.w + pv.w};
    *(float4*)(hb + base) = f;
    float o[4];
    ln_core(o, f, g, b, tid);
#pragma unroll
    for (int j = 0; j < 4; j += 2)
        *(__half2*)(y + base + j) = __halves2half2(__float2half_rn(o[j]), __float2half_rn(o[j+1]));
}

// ---------------- fp16 mma.sync GEMM 256x128, Kc=64, SW128, x3, 512 thr ------
static constexpr int A_TILE = 256 * 64 * 2;
static constexpr int B_TILE = 128 * 64 * 2;
static constexpr int S_A = 0, S_B = A_TILE;
static constexpr int STAGEB = A_TILE + B_TILE;
static constexpr int GEMM_SMEM = 3 * STAGEB;

__device__ __forceinline__ void tileA_cpa(const fp16* __restrict__ g,
                                          int row0, int stride, int k0,
                                          uint32_t sdst, int tid) {
#pragma unroll
    for (int i = 0; i < 4; i++) {
        int idx = i * 512 + tid;
        int r = idx >> 3, c = idx & 7;
        CPA(sdst + swz(r * 128 + c * 16), g + (size_t)(row0 + r) * stride + k0 + c * 8);
    }
}
__device__ __forceinline__ void tileB_cpa(const fp16* __restrict__ g,
                                          int row0, int stride, int k0,
                                          uint32_t sdst, int tid) {
#pragma unroll
    for (int i = 0; i < 2; i++) {
        int idx = i * 512 + tid;
        int r = idx >> 3, c = idx & 7;
        CPA(sdst + swz(r * 128 + c * 16), g + (size_t)(row0 + r) * stride + k0 + c * 8);
    }
}

__global__ __launch_bounds__(512, 1) void gemm_mma_kernel(
    const fp16* __restrict__ A, const fp16* __restrict__ Bm,
    const float* __restrict__ bias, const float* __restrict__ r1,
    const float* __restrict__ r2, float* __restrict__ C,
    fp16* __restrict__ Ch, int NN, int KK, int act) {
    extern __shared__ char smem[];
    const uint32_t sb = smem_u32(smem);
    const int tid = threadIdx.x;
    const int wid = tid >> 5, lane = tid & 31;
    const int wm = wid >> 2, wn = wid & 3;
    const int rowBase = blockIdx.y * 256, colBase = blockIdx.x * 128;

    float acc[4][4][4];
#pragma unroll
    for (int i = 0; i < 4; i++)
#pragma unroll
        for (int j = 0; j < 4; j++)
#pragma unroll
            for (int q = 0; q < 4; q++) acc[i][j][q] = 0.f;

    const uint32_t a_row = (uint32_t)((wm * 64 + (lane & 15)) * 128);
    const uint32_t a_col = (uint32_t)((lane >> 4) * 16);
    const uint32_t b_row0 = (uint32_t)((wn * 32 + (lane & 7) + ((lane >> 4) << 3)) * 128);
    const uint32_t b_col = (uint32_t)(((lane >> 3) & 1) * 16);

    const int nc = KK / 64;
    tileA_cpa(A,  rowBase, KK, 0, sb + S_A, tid);
    tileB_cpa(Bm, colBase, KK, 0, sb + S_B, tid);
    CPA_COMMIT();
    {
        uint32_t st = sb + STAGEB;
        tileA_cpa(A,  rowBase, KK, 64, st + S_A, tid);
        tileB_cpa(Bm, colBase, KK, 64, st + S_B, tid);
    }
    CPA_COMMIT();

    for (int c = 0; c < nc; c++) {
        if (c + 1 < nc) CPA_WAIT1(); else CPA_WAIT0();
        __syncthreads();
        if (c + 2 < nc) {
            uint32_t st = sb + ((c + 2) % 3) * STAGEB;
            int k0 = (c + 2) * 64;
            tileA_cpa(A,  rowBase, KK, k0, st + S_A, tid);
            tileB_cpa(Bm, colBase, KK, k0, st + S_B, tid);
            CPA_COMMIT();
        }
        uint32_t st = sb + (c % 3) * STAGEB;

#pragma unroll
        for (int ks = 0; ks < 4; ks++) {
            const uint32_t kb = ks * 32;
            uint32_t bh[2][4];
#pragma unroll
            for (int g = 0; g < 2; g++) {
                uint32_t roff = b_row0 + (uint32_t)(g * 16 * 128);
                ldsm4(bh[g], st + S_B + smx(roff, kb + b_col));
            }
#pragma unroll
            for (int mi = 0; mi < 4; mi++) {
                uint32_t roff = a_row + (uint32_t)(mi * 16 * 128);
                uint32_t af[4];
                ldsm4(af, st + S_A + smx(roff, kb + a_col));
#pragma unroll
                for (int nj = 0; nj < 4; nj++) {
                    int g = nj >> 1, o = (nj & 1) * 2;
                    mma16816h(acc[mi][nj], af, bh[g][o], bh[g][o + 1]);
                }
            }
        }
    }

    const int tq = lane >> 2, tr = lane & 3;
#pragma unroll
    for (int mi = 0; mi < 4; mi++) {
#pragma unroll
        for (int nj = 0; nj < 4; nj++) {
            int n = colBase + wn * 32 + nj * 8 + tr * 2;
            float2 bb = *(const float2*)(bias + n);
#pragma unroll
            for (int half = 0; half < 2; half++) {
                int m = rowBase + wm * 64 + mi * 16 + tq + half * 8;
                size_t base = (size_t)m * NN + n;
                float v0 = acc[mi][nj][half * 2 + 0] + bb.x;
                float v1 = acc[mi][nj][half * 2 + 1] + bb.y;
                if (act == 1) { v0 = v0 * normcdff(v0); v1 = v1 * normcdff(v1); }
                if (r1) { float2 q = *(const float2*)(r1 + base); v0 += q.x; v1 += q.y; }
                if (r2) { float2 q = *(const float2*)(r2 + base); v0 += q.x; v1 += q.y; }
                if (C) { float2 ov = {v0, v1}; *(float2*)(C + base) = ov; }
                if (Ch)
                    *(__half2*)(Ch + base) = __halves2half2(__float2half_rn(v0), __float2half_rn(v1));
            }
        }
    }
}

// ---------------- tensor-core attention (QT=128, fp16 score smem) ------------
static constexpr int QT = 128;
static constexpr int SCS2 = 520;                 // fp16 elements per row
static constexpr int AO_Q  = 0;                  // 128 rows x 128 B = 16384
static constexpr int AO_KV = 16384;              // 2 stages x 8192
static constexpr int AO_SC = 32768;              // 128*520*2 = 133120
static constexpr int ATTN_SMEM = 165888;

__device__ __forceinline__ void tile64_cpa(const fp16* __restrict__ g,
                                           int row0, int stride, uint32_t sdst, int tid) {
#pragma unroll
    for (int i = 0; i < 2; i++) {
        int idx = i * 256 + tid;
        int r = idx >> 3, c = idx & 7;
        CPA(sdst + swz(r * 128 + c * 16), g + (size_t)(row0 + r) * stride + c * 8);
    }
}

__global__ __launch_bounds__(256, 1) void attn_mma_kernel(
    const fp16* __restrict__ qkv, const float* __restrict__ bias,
    fp16* __restrict__ Ctx) {
    extern __shared__ char smem[];
    const uint32_t sb = smem_u32(smem);
    const int tid = threadIdx.x;
    const int wid = tid >> 5, lane = tid & 31;
    const int wm = wid >> 2, wn = wid & 3;           // wm: 2 x 64 rows; wn: 4 x 16 cols
    const int q0 = blockIdx.x * QT, h = blockIdx.y, b = blockIdx.z;
    const size_t base3 = (size_t)(b * S_) * D3 + h * DH_;
    const fp16* Q = qkv + base3;
    const fp16* K = qkv + base3 + D_;
    const fp16* V = qkv + base3 + 2 * D_;
    const int tq = lane >> 2, tr = lane & 3;

    // Q tile 128x64 fp16 = 128 rows x 128 B
    {
#pragma unroll
        for (int i = 0; i < 4; i++) {
            int idx = i * 256 + tid;
            int r = idx >> 3, c = idx & 7;
            CPA(sb + AO_Q + swz(r * 128 + c * 16), Q + (size_t)(q0 + r) * D3 + c * 8);
        }
    }
    tile64_cpa(K, 0, D3, sb + AO_KV, tid);
    CPA_COMMIT();
    CPA_WAIT0();
    __syncthreads();

    uint32_t qf[4][4][4];
    {
        uint32_t acol = (uint32_t)((lane >> 4) * 16);
#pragma unroll
        for (int mi = 0; mi < 4; mi++) {
            uint32_t arow = (uint32_t)((wm * 64 + mi * 16 + (lane & 15)) * 128);
#pragma unroll
            for (int ks = 0; ks < 4; ks++)
                ldsm4(qf[mi][ks], sb + AO_Q + smx(arow, ks * 32 + acol));
        }
    }

    fp16* sc16 = (fp16*)(smem + AO_SC);
    const uint32_t b_row = (uint32_t)((wn * 16 + (lane & 7) + ((lane >> 4) << 3)) * 128);
    const uint32_t b_col = (uint32_t)(((lane >> 3) & 1) * 16);
    for (int c = 0; c < 8; c++) {
        if (c < 7) {
            uint32_t st = sb + AO_KV + ((c + 1) & 1) * 8192;
            tile64_cpa(K, (c + 1) * 64, D3, st, tid);
            CPA_COMMIT();
            CPA_WAIT1();
        } else {
            CPA_WAIT0();
        }
        __syncthreads();
        uint32_t st = sb + AO_KV + (c & 1) * 8192;

        float acc[4][2][4] = {};
#pragma unroll
        for (int ks = 0; ks < 4; ks++) {
            uint32_t kh4[4];
            ldsm4(kh4, st + smx(b_row, ks * 32 + b_col));
#pragma unroll
            for (int mi = 0; mi < 4; mi++)
#pragma unroll
                for (int nj = 0; nj < 2; nj++)
                    mma16816h(acc[mi][nj], qf[mi][ks], kh4[nj * 2], kh4[nj * 2 + 1]);
        }
#pragma unroll
        for (int mi = 0; mi < 4; mi++) {
#pragma unroll
            for (int nj = 0; nj < 2; nj++) {
                int kg = c * 64 + wn * 16 + nj * 8 + tr * 2;
#pragma unroll
                for (int half = 0; half < 2; half++) {
                    int m = wm * 64 + mi * 16 + tq + half * 8;
                    int rel = (q0 + m) - kg + (P_ - 1);
                    float s0 = acc[mi][nj][half*2+0] * 0.125f + __ldg(&bias[rel * H_ + h]);
                    float s1 = acc[mi][nj][half*2+1] * 0.125f + __ldg(&bias[(rel - 1) * H_ + h]);
                    *(__half2*)(sc16 + (size_t)m * SCS2 + kg) =
                        __halves2half2(__float2half_rn(s0), __float2half_rn(s1));
                }
            }
        }
        __syncthreads();
    }

    tile64_cpa(V, 0, D3, sb + AO_KV, tid);
    CPA_COMMIT();

    // softmax: 8 warps x 16 rows; fp32 math, single fp16 rounding on output
    {
#pragma unroll
        for (int rr = 0; rr < 16; rr++) {
            int r = wid * 16 + rr;
            fp16* row = sc16 + (size_t)r * SCS2;
            float v[16];
#pragma unroll
            for (int i = 0; i < 16; i++) v[i] = __half2float(row[lane + i * 32]);
            float mx = -1e30f;
#pragma unroll
            for (int i = 0; i < 16; i++) mx = fmaxf(mx, v[i]);
#pragma unroll
            for (int o = 16; o > 0; o >>= 1) mx = fmaxf(mx, __shfl_xor_sync(0xffffffffu, mx, o));
            float sum = 0.f;
#pragma unroll
            for (int i = 0; i < 16; i++) { v[i] = expf(v[i] - mx); sum += v[i]; }
#pragma unroll
            for (int o = 16; o > 0; o >>= 1) sum += __shfl_xor_sync(0xffffffffu, sum, o);
            float inv = 1.0f / sum;
#pragma unroll
            for (int i = 0; i < 16; i++) row[lane + i * 32] = __float2half_rn(v[i] * inv);
        }
    }
    __syncthreads();

    float cacc[4][2][4] = {};
    const uint32_t v_row = (uint32_t)(((lane & 7) + ((lane >> 3) & 1) * 8) * 128);
    const uint32_t v_col = (uint32_t)(wn * 32 + (lane >> 4) * 16);
    for (int c = 0; c < 8; c++) {
        if (c < 7) {
            uint32_t st = sb + AO_KV + ((c + 1) & 1) * 8192;
            tile64_cpa(V, (c + 1) * 64, D3, st, tid);
            CPA_COMMIT();
            CPA_WAIT1();
        } else {
            CPA_WAIT0();
        }
        __syncthreads();
        uint32_t st = sb + AO_KV + (c & 1) * 8192;

#pragma unroll
        for (int ks = 0; ks < 4; ks++) {
            uint32_t vh4[4];
            ldsm4t(vh4, st + smx(v_row + (uint32_t)(ks * 16 * 128), v_col));
#pragma unroll
            for (int mi = 0; mi < 4; mi++) {
                uint32_t aw_row = (uint32_t)((wm * 64 + mi * 16 + (lane & 15)) * (SCS2 * 2));
                uint32_t awoff = aw_row + (uint32_t)((c * 64 + ks * 16 + (lane >> 4) * 8) * 2);
                uint32_t ah4[4];
                ldsm4(ah4, (uint32_t)(sb + AO_SC) + awoff);
#pragma unroll
                for (int nj = 0; nj < 2; nj++)
                    mma16816h(cacc[mi][nj], ah4, vh4[nj * 2], vh4[nj * 2 + 1]);
            }
        }
        __syncthreads();
    }

#pragma unroll
    for (int mi = 0; mi < 4; mi++) {
#pragma unroll
        for (int nj = 0; nj < 2; nj++) {
            int n = wn * 16 + nj * 8 + tr * 2;
#pragma unroll
            for (int half = 0; half < 2; half++) {
                int m = wm * 64 + mi * 16 + tq + half * 8;
                size_t gidx = (size_t)(b * S_ + q0 + m) * D_ + h * DH_ + n;
                *(__half2*)(Ctx + gidx) = __halves2half2(
                    __float2half_rn(cacc[mi][nj][half*2+0]), __float2half_rn(cacc[mi][nj][half*2+1]));
            }
        }
    }
}

// ---------------- launch ----------------------------------------------------
extern "C" void kernel_launch(void* const* d_in, const int* in_sizes, int n_in,
                              void* d_out, int out_size) {
    (void)in_sizes; (void)n_in; (void)out_size;
    const float* x    = (const float*)d_in[0];
    const float* pe   = (const float*)d_in[1];
    const float* wq   = (const float*)d_in[2];
    const float* bq   = (const float*)d_in[3];
    const float* wk   = (const float*)d_in[4];
    const float* bk   = (const float*)d_in[5];
    const float* wv   = (const float*)d_in[6];
    const float* bv   = (const float*)d_in[7];
    const float* wo   = (const float*)d_in[8];
    const float* bo   = (const float*)d_in[9];
    const float* bt   = (const float*)d_in[10];
    const float* w1   = (const float*)d_in[11];
    const float* b1   = (const float*)d_in[12];
    const float* w2   = (const float*)d_in[13];
    const float* b2   = (const float*)d_in[14];
    const float* ln1g = (const float*)d_in[15];
    const float* ln1b = (const float*)d_in[16];
    const float* ln2g = (const float*)d_in[17];
    const float* ln2b = (const float*)d_in[18];
    float* out = (float*)d_out;

    float *hb, *o1, *bqkv;
    fp16 *xn, *qkv, *cx, *f1, *wqkvp, *wop, *w1p, *w2p;
    cudaGetSymbolAddress((void**)&hb,   g_h);
    cudaGetSymbolAddress((void**)&o1,   g_out1);
    cudaGetSymbolAddress((void**)&bqkv, g_bqkv);
    cudaGetSymbolAddress((void**)&xn,   g_xn);
    cudaGetSymbolAddress((void**)&qkv,  g_qkv);
    cudaGetSymbolAddress((void**)&cx,   g_ctx);
    cudaGetSymbolAddress((void**)&f1,   g_f1);
    cudaGetSymbolAddress((void**)&wqkvp, g_wqkvT);
    cudaGetSymbolAddress((void**)&wop,  g_woT);
    cudaGetSymbolAddress((void**)&w1p,  g_w1T);
    cudaGetSymbolAddress((void**)&w2p,  g_w2T);

    cudaFuncSetAttribute(attn_mma_kernel, cudaFuncAttributeMaxDynamicSharedMemorySize, ATTN_SMEM);
    cudaFuncSetAttribute(gemm_mma_kernel, cudaFuncAttributeMaxDynamicSharedMemorySize, GEMM_SMEM);

    dim3 gQKV(D3 / 128, M_ / 256);
    dim3 gD(D_ / 128, M_ / 256);
    dim3 gF(F_ / 128, M_ / 256);
    dim3 gAttn(S_ / QT, H_, B_);   // (4, 16, 16)

    packb_kernel<<<dim3(D_ / 256, L_), 256>>>(bq, bk, bv, bqkv);
    wtransqkv_kernel<<<dim3(32, 32, 3 * L_), 256>>>(wq, wk, wv, wqkvp);
    wtrans_kernel<<<dim3(32, 32, L_), 256>>>(wo, wop, D_, D_, (size_t)D_ * D_);
    wtrans_kernel<<<dim3(F_ / 32, D_ / 32, L_), 256>>>(w1, w1p, D_, F_, (size_t)D_ * F_);
    wtrans_kernel<<<dim3(D_ / 32, F_ / 32, L_), 256>>>(w2, w2p, F_, D_, (size_t)F_ * D_);

    for (int l = 0; l < L_; l++) {
        size_t oQKV = (size_t)l * D3 * D_;
        size_t oDD  = (size_t)l * D_ * D_;
        size_t oDF  = (size_t)l * D_ * F_;
        size_t oD   = (size_t)l * D_;
        size_t oF   = (size_t)l * F_;

        if (l == 0)
            ln0_kernel<<<M_, 256>>>(x, pe, ln1g, ln1b, hb, xn);
        else
            ln_kernel<<<M_, 256>>>(hb, ln1g + oD, ln1b + oD, xn);
        gemm_mma_kernel<<<gQKV, 512, GEMM_SMEM>>>(xn, wqkvp + oQKV,
            bqkv + (size_t)l * D3, nullptr, nullptr, nullptr, qkv, D3, D_, 0);

        attn_mma_kernel<<<gAttn, 256, ATTN_SMEM>>>(qkv,
            bt + (size_t)l * (2 * P_ - 1) * H_, cx);

        gemm_mma_kernel<<<gD, 512, GEMM_SMEM>>>(cx, wop + oDD,
            bo + oD, hb, nullptr, o1, nullptr, D_, D_, 0);

        ln_kernel<<<M_, 256>>>(o1, ln2g + oD, ln2b + oD, xn);
        gemm_mma_kernel<<<gF, 512, GEMM_SMEM>>>(xn, w1p + oDF,
            b1 + oF, nullptr, nullptr, nullptr, f1, F_, D_, 1);
        float* dst = (l == L_ - 1) ? out : hb;
        gemm_mma_kernel<<<gD, 512, GEMM_SMEM>>>(f1, w2p + oDF,
            b2 + oD, o1, hb, dst, nullptr, D_, F_, 0);
    }
}